// round 2
// baseline (speedup 1.0000x reference)
#include <cuda_runtime.h>
#include <math.h>

#define Bq 128
#define Lq 64
#define Tq 48
#define Eq 512
#define Hq 512
#define Vq 32000
#define G4 2048   // 4*H
#define KP 512    // K per GEMM pair
#define NEGV (-1e9f)

// ---------------- scratch (__device__ globals; no allocations allowed) ----------------
__device__ float g_G0[Bq * Lq * G4];     // precomputed x@Wih0^T + b0 for encoder layer0 (64MB)
__device__ float g_gates[Bq * G4];       // per-step gate preactivations
__device__ float g_h1[Bq * Hq], g_c1[Bq * Hq];
__device__ float g_h2[Bq * Hq], g_c2[Bq * Hq];
__device__ float g_nh1[Bq * Hq];         // unmasked layer0 output (feeds layer1)
__device__ float g_S[Bq * Lq * Hq];      // src_states (B, L, H), zero where masked (16MB)
__device__ float g_dh[Bq * Hq], g_dc[Bq * Hq];
__device__ float g_av[Bq * Hq], g_ctx[Bq * Hq];
__device__ float g_logits[Bq * Vq];      // per-step logits (16.4MB)
__device__ float g_nllbuf[(Tq - 1) * Bq];

// ---------------- generic fp32 tiled GEMM ----------------
// C[M,N] = (init ? init[m,n] : 0) + (bias ? bias[n] : 0)
//          + sum_p  A_p[m, 0:512] @ W_p[n, 0:512]^T
// Optional row gather for each pair: row base = map[m*ms] (embedding lookup).
template <int TM, int TN>
__global__ __launch_bounds__(256) void gemm_k(
    float* __restrict__ C, int M, int N,
    const float* __restrict__ init, int init_stride,
    const float* __restrict__ bias,
    int npairs,
    const float* A0, const int* map0, int ms0, const float* W0, int ldw0,
    const float* A1, const int* map1, int ms1, const float* W1, int ldw1,
    const float* A2, const int* map2, int ms2, const float* W2, int ldw2)
{
    constexpr int BM = 16 * TM, BN = 16 * TN;
    constexpr int SA = BM + 4, SB = BN + 4;   // strides are multiples of 4 floats -> 16B aligned rows
    __shared__ float As[16][SA];
    __shared__ float Ws[16][SB];

    const int m0 = blockIdx.x * BM;
    const int n0 = blockIdx.y * BN;
    const int tid = threadIdx.x;
    const int tx = tid & 15, ty = tid >> 4;

    float acc[TM][TN];
#pragma unroll
    for (int i = 0; i < TM; i++)
#pragma unroll
        for (int j = 0; j < TN; j++) acc[i][j] = 0.f;

    const float* Aps[3] = {A0, A1, A2};
    const int*   Mps[3] = {map0, map1, map2};
    const int    Mss[3] = {ms0, ms1, ms2};
    const float* Wps[3] = {W0, W1, W2};
    const int    Lws[3] = {ldw0, ldw1, ldw2};

    for (int p = 0; p < npairs; p++) {
        const float* A = Aps[p];
        const int* mp = Mps[p];
        const int ms = Mss[p];
        const float* W = Wps[p];
        const int ldw = Lws[p];

        for (int k0 = 0; k0 < KP; k0 += 16) {
            // load A tile (BM x 16), transposed into smem
#pragma unroll
            for (int e = tid; e < BM * 16; e += 256) {
                int r = e >> 4, c = e & 15;
                int gm = m0 + r;
                long arow = mp ? (long)mp[(long)gm * ms] * KP : (long)gm * KP;
                As[c][r] = A[arow + k0 + c];
            }
            // load W tile (BN x 16), transposed
#pragma unroll
            for (int e = tid; e < BN * 16; e += 256) {
                int r = e >> 4, c = e & 15;
                Ws[c][r] = W[(long)(n0 + r) * ldw + k0 + c];
            }
            __syncthreads();

#pragma unroll
            for (int k = 0; k < 16; k++) {
                float a[TM], w[TN];
                if constexpr (TM == 4) {
                    float4 v = *reinterpret_cast<const float4*>(&As[k][ty * 4]);
                    a[0] = v.x; a[1] = v.y; a[2] = v.z; a[3] = v.w;
                } else {
                    float2 v = *reinterpret_cast<const float2*>(&As[k][ty * 2]);
                    a[0] = v.x; a[1] = v.y;
                }
                if constexpr (TN == 4) {
                    float4 v = *reinterpret_cast<const float4*>(&Ws[k][tx * 4]);
                    w[0] = v.x; w[1] = v.y; w[2] = v.z; w[3] = v.w;
                } else {
                    float2 v = *reinterpret_cast<const float2*>(&Ws[k][tx * 2]);
                    w[0] = v.x; w[1] = v.y;
                }
#pragma unroll
                for (int i = 0; i < TM; i++)
#pragma unroll
                    for (int j = 0; j < TN; j++) acc[i][j] = fmaf(a[i], w[j], acc[i][j]);
            }
            __syncthreads();
        }
    }

#pragma unroll
    for (int i = 0; i < TM; i++) {
        int m = m0 + ty * TM + i;
        if (m >= M) continue;
#pragma unroll
        for (int j = 0; j < TN; j++) {
            int n = n0 + tx * TN + j;
            float v = acc[i][j];
            if (init) v += init[(long)m * init_stride + n];
            if (bias) v += bias[n];
            C[(long)m * N + n] = v;
        }
    }
}

// ---------------- LSTM cell (pointwise) ----------------
// gates layout: [i(0:H) | f(H:2H) | g(2H:3H) | o(3H:4H)] per batch row.
// masked update: h,c updated only where t < lens[b] (lens==nullptr -> always).
__global__ __launch_bounds__(256) void cell_k(
    const float* __restrict__ gates,
    float* __restrict__ h, float* __restrict__ c,
    float* __restrict__ nh_out,   // nullable: unmasked new h
    float* __restrict__ S_out,    // nullable: src_states write (masked to 0)
    const int* __restrict__ lens, int t)
{
    int idx = blockIdx.x * 256 + threadIdx.x;
    if (idx >= Bq * Hq) return;
    int b = idx >> 9;
    int j = idx & 511;
    const float* g = gates + (long)b * G4;
    float gi = g[j], gf = g[Hq + j], gg = g[2 * Hq + j], go = g[3 * Hq + j];
    float i_ = 1.f / (1.f + expf(-gi));
    float f_ = 1.f / (1.f + expf(-gf));
    float t_ = tanhf(gg);
    float o_ = 1.f / (1.f + expf(-go));
    float cn = f_ * c[idx] + i_ * t_;
    float hn = o_ * tanhf(cn);
    bool m = lens ? (t < lens[b]) : true;
    if (nh_out) nh_out[idx] = hn;
    if (S_out) S_out[(long)b * Lq * Hq + (long)t * Hq + j] = m ? hn : 0.f;
    if (m) { h[idx] = hn; c[idx] = cn; }
}

__global__ void init_zero_k(float* h1, float* c1, float* h2, float* c2, float* av)
{
    int i = blockIdx.x * 256 + threadIdx.x;
    if (i < Bq * Hq) { h1[i] = 0.f; c1[i] = 0.f; h2[i] = 0.f; c2[i] = 0.f; av[i] = 0.f; }
}

__global__ void tanh_k(float* __restrict__ dh, const float* __restrict__ dc)
{
    int i = blockIdx.x * 256 + threadIdx.x;
    if (i < Bq * Hq) dh[i] = tanhf(dc[i]);
}

// ---------------- attention: scores, masked softmax, context ----------------
// one block per batch row
__global__ __launch_bounds__(256) void attn_k(
    const float* __restrict__ dh, const float* __restrict__ S,
    const int* __restrict__ slens, float* __restrict__ ctx)
{
    int b = blockIdx.x;
    __shared__ float sh[Hq];
    __shared__ float part[Lq][4];
    __shared__ float sc[Lq];
    __shared__ float sinv;
    int tid = threadIdx.x;
    sh[tid] = dh[(long)b * Hq + tid];
    sh[tid + 256] = dh[(long)b * Hq + tid + 256];
    __syncthreads();

    int l = tid >> 2, q = tid & 3;
    const float* Sb = S + (long)b * Lq * Hq + (long)l * Hq + q * 128;
    float p = 0.f;
#pragma unroll 8
    for (int k = 0; k < 128; k++) p = fmaf(sh[q * 128 + k], Sb[k], p);
    part[l][q] = p;
    __syncthreads();

    if (tid < Lq) {
        float s = part[tid][0] + part[tid][1] + part[tid][2] + part[tid][3];
        if (tid >= slens[b]) s = NEGV;
        sc[tid] = expf(s);   // scores are O(0.1); expf(-1e9) flushes to 0
    }
    __syncthreads();
    if (tid == 0) {
        float tsum = 0.f;
        for (int i = 0; i < Lq; i++) tsum += sc[i];
        sinv = 1.f / tsum;
    }
    __syncthreads();
    if (tid < Lq) sc[tid] *= sinv;
    __syncthreads();

    for (int j = tid; j < Hq; j += 256) {
        const float* Sb2 = S + (long)b * Lq * Hq + j;
        float acc = 0.f;
#pragma unroll 8
        for (int l2 = 0; l2 < Lq; l2++) acc = fmaf(sc[l2], Sb2[(long)l2 * Hq], acc);
        ctx[(long)b * Hq + j] = acc;
    }
}

// ---------------- NLL from logits (deterministic, per-row block) ----------------
__global__ __launch_bounds__(256) void nll_k(
    const float* __restrict__ logits, const int* __restrict__ trg_tokens,
    const int* __restrict__ trg_lens, int s)
{
    int b = blockIdx.x;
    __shared__ float sm[256];
    const float* row = logits + (long)b * Vq;
    float acc = 0.f;
    for (int n = threadIdx.x; n < Vq; n += 256) acc += expf(row[n]);  // |logit| << 1, safe without max-shift
    sm[threadIdx.x] = acc;
    __syncthreads();
    for (int st = 128; st > 0; st >>= 1) {
        if (threadIdx.x < st) sm[threadIdx.x] += sm[threadIdx.x + st];
        __syncthreads();
    }
    if (threadIdx.x == 0) {
        int tgt = trg_tokens[b * Tq + s + 1];
        float nll = logf(sm[0]) - row[tgt];
        g_nllbuf[s * Bq + b] = ((s + 1) < trg_lens[b]) ? -nll : 0.f;
    }
}

__global__ __launch_bounds__(256) void reduce_k(float* __restrict__ out)
{
    __shared__ float sm[256];
    float t = 0.f;
    for (int i = threadIdx.x; i < (Tq - 1) * Bq; i += 256) t += g_nllbuf[i];
    sm[threadIdx.x] = t;
    __syncthreads();
    for (int st = 128; st > 0; st >>= 1) {
        if (threadIdx.x < st) sm[threadIdx.x] += sm[threadIdx.x + st];
        __syncthreads();
    }
    if (threadIdx.x == 0) out[0] = sm[0];
}

// ---------------- launch ----------------
extern "C" void kernel_launch(void* const* d_in, const int* in_sizes, int n_in,
                              void* d_out, int out_size)
{
    const int*   src_tokens = (const int*)d_in[0];
    const int*   src_lens   = (const int*)d_in[1];
    const int*   trg_tokens = (const int*)d_in[2];
    const int*   trg_lens   = (const int*)d_in[3];
    const float* src_emb    = (const float*)d_in[4];
    const float* trg_emb    = (const float*)d_in[5];
    const float* enc_Wih0   = (const float*)d_in[6];
    const float* enc_Whh0   = (const float*)d_in[7];
    const float* enc_b0     = (const float*)d_in[8];
    const float* enc_Wih1   = (const float*)d_in[9];
    const float* enc_Whh1   = (const float*)d_in[10];
    const float* enc_b1     = (const float*)d_in[11];
    const float* dec_Wih    = (const float*)d_in[12];
    const float* dec_Whh    = (const float*)d_in[13];
    const float* dec_b      = (const float*)d_in[14];
    const float* hid_W      = (const float*)d_in[15];
    const float* hid_b      = (const float*)d_in[16];
    const float* out_W      = (const float*)d_in[17];
    const float* out_b      = (const float*)d_in[18];
    const float* init_W     = (const float*)d_in[19];
    const float* init_b     = (const float*)d_in[20];

    float *G0, *gates, *h1, *c1, *h2, *c2, *nh1, *S, *dh, *dc, *av, *ctx, *logits;
    cudaGetSymbolAddress((void**)&G0, g_G0);
    cudaGetSymbolAddress((void**)&gates, g_gates);
    cudaGetSymbolAddress((void**)&h1, g_h1);
    cudaGetSymbolAddress((void**)&c1, g_c1);
    cudaGetSymbolAddress((void**)&h2, g_h2);
    cudaGetSymbolAddress((void**)&c2, g_c2);
    cudaGetSymbolAddress((void**)&nh1, g_nh1);
    cudaGetSymbolAddress((void**)&S, g_S);
    cudaGetSymbolAddress((void**)&dh, g_dh);
    cudaGetSymbolAddress((void**)&dc, g_dc);
    cudaGetSymbolAddress((void**)&av, g_av);
    cudaGetSymbolAddress((void**)&ctx, g_ctx);
    cudaGetSymbolAddress((void**)&logits, g_logits);

    const int cellBlocks = (Bq * Hq + 255) / 256;

    // zero initial states (h1,c1,h2,c2, decoder av)
    init_zero_k<<<cellBlocks, 256>>>(h1, c1, h2, c2, av);

    // G0 = emb(src_tokens) @ Wih0^T + b0  (one big batched GEMM, M = B*L)
    gemm_k<4, 4><<<dim3(Bq * Lq / 64, G4 / 64), 256>>>(
        G0, Bq * Lq, G4, nullptr, 0, enc_b0, 1,
        src_emb, src_tokens, 1, enc_Wih0, KP,
        nullptr, nullptr, 0, nullptr, 0,
        nullptr, nullptr, 0, nullptr, 0);

    // ---------------- encoder recurrence ----------------
    for (int t = 0; t < Lq; t++) {
        // layer0 gates = G0[:,t,:] + h1 @ Whh0^T
        gemm_k<4, 2><<<dim3(Bq / 64, G4 / 32), 256>>>(
            gates, Bq, G4, G0 + (long)t * G4, Lq * G4, nullptr, 1,
            h1, nullptr, 0, enc_Whh0, KP,
            nullptr, nullptr, 0, nullptr, 0,
            nullptr, nullptr, 0, nullptr, 0);
        cell_k<<<cellBlocks, 256>>>(gates, h1, c1, nh1, nullptr, src_lens, t);

        // layer1 gates = nh1 @ Wih1^T + h2 @ Whh1^T + b1
        gemm_k<4, 2><<<dim3(Bq / 64, G4 / 32), 256>>>(
            gates, Bq, G4, nullptr, 0, enc_b1, 2,
            nh1, nullptr, 0, enc_Wih1, KP,
            h2, nullptr, 0, enc_Whh1, KP,
            nullptr, nullptr, 0, nullptr, 0);
        cell_k<<<cellBlocks, 256>>>(gates, h2, c2, nullptr, S, src_lens, t);
    }

    // ---------------- decoder init: c0 = [c1,c2] @ init_W^T + init_b; h0 = tanh(c0) ----------------
    gemm_k<2, 2><<<dim3(Bq / 32, Hq / 32), 256>>>(
        dc, Bq, Hq, nullptr, 0, init_b, 2,
        c1, nullptr, 0, init_W, 2 * Hq,
        c2, nullptr, 0, init_W + Hq, 2 * Hq,
        nullptr, nullptr, 0, nullptr, 0);
    tanh_k<<<cellBlocks, 256>>>(dh, dc);

    // ---------------- decoder steps ----------------
    for (int s = 0; s < Tq - 1; s++) {
        // gates = [v, av] @ dec_Wih^T + h @ dec_Whh^T + b   (v gathered from trg_emb)
        gemm_k<4, 2><<<dim3(Bq / 64, G4 / 32), 256>>>(
            gates, Bq, G4, nullptr, 0, dec_b, 3,
            trg_emb, trg_tokens + s, Tq, dec_Wih, Eq + Hq,
            av, nullptr, 0, dec_Wih + Eq, Eq + Hq,
            dh, nullptr, 0, dec_Whh, KP);
        cell_k<<<cellBlocks, 256>>>(gates, dh, dc, nullptr, nullptr, nullptr, 0);

        // attention -> ctx
        attn_k<<<Bq, 256>>>(dh, S, src_lens, ctx);

        // av = [h, ctx] @ hid_W^T + hid_b
        gemm_k<2, 2><<<dim3(Bq / 32, Hq / 32), 256>>>(
            av, Bq, Hq, nullptr, 0, hid_b, 2,
            dh, nullptr, 0, hid_W, 2 * Hq,
            ctx, nullptr, 0, hid_W + Hq, 2 * Hq,
            nullptr, nullptr, 0, nullptr, 0);

        // logits = av @ out_W^T + out_b
        gemm_k<4, 4><<<dim3(Bq / 64, Vq / 64), 256>>>(
            logits, Bq, Vq, nullptr, 0, out_b, 1,
            av, nullptr, 0, out_W, KP,
            nullptr, nullptr, 0, nullptr, 0,
            nullptr, nullptr, 0, nullptr, 0);

        // NLL for this step (masked)
        nll_k<<<Bq, 256>>>(logits, trg_tokens, trg_lens, s);
    }

    // final sum
    reduce_k<<<1, 256>>>((float*)d_out);
}

// round 4
// speedup vs baseline: 1.5820x; 1.5820x over previous
#include <cuda_runtime.h>
#include <cuda_bf16.h>
#include <math.h>
#include <stdint.h>
#include <cstdint>

#define Bq 128
#define Lq 64
#define Tq 48
#define Eq 512
#define Hq 512
#define Vq 32000
#define G4 2048   // 4*H
#define KP 512
#define NEGV (-1e9f)
#define NBLK (Vq / 128)   // 250 logits N-blocks

// ---------------- scratch ----------------
__device__ float g_G0[Bq * Lq * G4];
__device__ float g_gates[Bq * G4];
__device__ float g_h1[Bq * Hq], g_c1[Bq * Hq];
__device__ float g_h2[Bq * Hq], g_c2[Bq * Hq];
__device__ float g_nh1[Bq * Hq];
__device__ float g_S[Bq * Lq * Hq];
__device__ float g_dh[Bq * Hq], g_dc[Bq * Hq];
__device__ float g_av[Bq * Hq], g_ctx[Bq * Hq];
__device__ float g_nllbuf[(Tq - 1) * Bq];
__device__ __nv_bfloat16 g_avh[Bq * Hq];        // bf16 copy of av for logits GEMM
__device__ __nv_bfloat16 g_outWb[Vq * KP];      // bf16 out_W (32MB)
__device__ float g_part[NBLK * Bq];             // per-block exp-sum partials
__device__ float g_tgtlogit[Bq];

// ---------------- generic fp32 tiled GEMM ----------------
template <int TM, int TN>
__global__ __launch_bounds__(256) void gemm_k(
    float* __restrict__ C, int M, int N,
    const float* __restrict__ init, int init_stride,
    const float* __restrict__ bias,
    int npairs,
    const float* A0, const int* map0, int ms0, const float* W0, int ldw0,
    const float* A1, const int* map1, int ms1, const float* W1, int ldw1,
    const float* A2, const int* map2, int ms2, const float* W2, int ldw2)
{
    constexpr int BM = 16 * TM, BN = 16 * TN;
    constexpr int SA = BM + 4, SB = BN + 4;
    __shared__ float As[16][SA];
    __shared__ float Ws[16][SB];

    const int m0 = blockIdx.x * BM;
    const int n0 = blockIdx.y * BN;
    const int tid = threadIdx.x;
    const int tx = tid & 15, ty = tid >> 4;

    float acc[TM][TN];
#pragma unroll
    for (int i = 0; i < TM; i++)
#pragma unroll
        for (int j = 0; j < TN; j++) acc[i][j] = 0.f;

    const float* Aps[3] = {A0, A1, A2};
    const int*   Mps[3] = {map0, map1, map2};
    const int    Mss[3] = {ms0, ms1, ms2};
    const float* Wps[3] = {W0, W1, W2};
    const int    Lws[3] = {ldw0, ldw1, ldw2};

    for (int p = 0; p < npairs; p++) {
        const float* A = Aps[p];
        const int* mp = Mps[p];
        const int ms = Mss[p];
        const float* W = Wps[p];
        const int ldw = Lws[p];

        for (int k0 = 0; k0 < KP; k0 += 16) {
#pragma unroll
            for (int e = tid; e < BM * 16; e += 256) {
                int r = e >> 4, c = e & 15;
                int gm = m0 + r;
                long arow = mp ? (long)mp[(long)gm * ms] * KP : (long)gm * KP;
                As[c][r] = A[arow + k0 + c];
            }
#pragma unroll
            for (int e = tid; e < BN * 16; e += 256) {
                int r = e >> 4, c = e & 15;
                Ws[c][r] = W[(long)(n0 + r) * ldw + k0 + c];
            }
            __syncthreads();

#pragma unroll
            for (int k = 0; k < 16; k++) {
                float a[TM], w[TN];
                if constexpr (TM == 4) {
                    float4 v = *reinterpret_cast<const float4*>(&As[k][ty * 4]);
                    a[0] = v.x; a[1] = v.y; a[2] = v.z; a[3] = v.w;
                } else {
                    float2 v = *reinterpret_cast<const float2*>(&As[k][ty * 2]);
                    a[0] = v.x; a[1] = v.y;
                }
                if constexpr (TN == 4) {
                    float4 v = *reinterpret_cast<const float4*>(&Ws[k][tx * 4]);
                    w[0] = v.x; w[1] = v.y; w[2] = v.z; w[3] = v.w;
                } else {
                    float2 v = *reinterpret_cast<const float2*>(&Ws[k][tx * 2]);
                    w[0] = v.x; w[1] = v.y;
                }
#pragma unroll
                for (int i = 0; i < TM; i++)
#pragma unroll
                    for (int j = 0; j < TN; j++) acc[i][j] = fmaf(a[i], w[j], acc[i][j]);
            }
            __syncthreads();
        }
    }

#pragma unroll
    for (int i = 0; i < TM; i++) {
        int m = m0 + ty * TM + i;
        if (m >= M) continue;
#pragma unroll
        for (int j = 0; j < TN; j++) {
            int n = n0 + tx * TN + j;
            float v = acc[i][j];
            if (init) v += init[(long)m * init_stride + n];
            if (bias) v += bias[n];
            C[(long)m * N + n] = v;
        }
    }
}

// ---------------- LSTM cell ----------------
__global__ __launch_bounds__(256) void cell_k(
    const float* __restrict__ gates,
    float* __restrict__ h, float* __restrict__ c,
    float* __restrict__ nh_out, float* __restrict__ S_out,
    const int* __restrict__ lens, int t)
{
    int idx = blockIdx.x * 256 + threadIdx.x;
    if (idx >= Bq * Hq) return;
    int b = idx >> 9;
    int j = idx & 511;
    const float* g = gates + (long)b * G4;
    float gi = g[j], gf = g[Hq + j], gg = g[2 * Hq + j], go = g[3 * Hq + j];
    float i_ = 1.f / (1.f + expf(-gi));
    float f_ = 1.f / (1.f + expf(-gf));
    float t_ = tanhf(gg);
    float o_ = 1.f / (1.f + expf(-go));
    float cn = f_ * c[idx] + i_ * t_;
    float hn = o_ * tanhf(cn);
    bool m = lens ? (t < lens[b]) : true;
    if (nh_out) nh_out[idx] = hn;
    if (S_out) S_out[(long)b * Lq * Hq + (long)t * Hq + j] = m ? hn : 0.f;
    if (m) { h[idx] = hn; c[idx] = cn; }
}

__global__ void init_zero_k(float* h1, float* c1, float* h2, float* c2, float* av)
{
    int i = blockIdx.x * 256 + threadIdx.x;
    if (i < Bq * Hq) { h1[i] = 0.f; c1[i] = 0.f; h2[i] = 0.f; c2[i] = 0.f; av[i] = 0.f; }
}

__global__ void tanh_k(float* __restrict__ dh, const float* __restrict__ dc)
{
    int i = blockIdx.x * 256 + threadIdx.x;
    if (i < Bq * Hq) dh[i] = tanhf(dc[i]);
}

__global__ void f2bf_k(const float* __restrict__ in, __nv_bfloat16* __restrict__ out, int n)
{
    int i = blockIdx.x * 256 + threadIdx.x;
    if (i < n) out[i] = __float2bfloat16_rn(in[i]);
}

// ---------------- attention ----------------
__global__ __launch_bounds__(256) void attn_k(
    const float* __restrict__ dh, const float* __restrict__ S,
    const int* __restrict__ slens, float* __restrict__ ctx)
{
    int b = blockIdx.x;
    __shared__ float sh[Hq];
    __shared__ float part[Lq][4];
    __shared__ float sc[Lq];
    __shared__ float sinv;
    int tid = threadIdx.x;
    sh[tid] = dh[(long)b * Hq + tid];
    sh[tid + 256] = dh[(long)b * Hq + tid + 256];
    __syncthreads();

    int l = tid >> 2, q = tid & 3;
    const float* Sb = S + (long)b * Lq * Hq + (long)l * Hq + q * 128;
    float p = 0.f;
#pragma unroll 8
    for (int k = 0; k < 128; k++) p = fmaf(sh[q * 128 + k], Sb[k], p);
    part[l][q] = p;
    __syncthreads();

    if (tid < Lq) {
        float s = part[tid][0] + part[tid][1] + part[tid][2] + part[tid][3];
        if (tid >= slens[b]) s = NEGV;
        sc[tid] = expf(s);
    }
    __syncthreads();
    if (tid == 0) {
        float tsum = 0.f;
        for (int i = 0; i < Lq; i++) tsum += sc[i];
        sinv = 1.f / tsum;
    }
    __syncthreads();
    if (tid < Lq) sc[tid] *= sinv;
    __syncthreads();

    for (int j = tid; j < Hq; j += 256) {
        const float* Sb2 = S + (long)b * Lq * Hq + j;
        float acc = 0.f;
#pragma unroll 8
        for (int l2 = 0; l2 < Lq; l2++) acc = fmaf(sc[l2], Sb2[(long)l2 * Hq], acc);
        ctx[(long)b * Hq + j] = acc;
    }
}

// ---------------- bf16 HMMA logits GEMM with fused exp-sum / target-logit epilogue ----
#define LSTRIDE 72   // bf16 elements per smem row (64 data + 8 pad)

__device__ __forceinline__ void ldsm4(unsigned int* r, unsigned int addr) {
    asm volatile("ldmatrix.sync.aligned.m8n8.x4.shared.b16 {%0,%1,%2,%3}, [%4];"
                 : "=r"(r[0]), "=r"(r[1]), "=r"(r[2]), "=r"(r[3]) : "r"(addr));
}
__device__ __forceinline__ void ldsm2(unsigned int* r, unsigned int addr) {
    asm volatile("ldmatrix.sync.aligned.m8n8.x2.shared.b16 {%0,%1}, [%2];"
                 : "=r"(r[0]), "=r"(r[1]) : "r"(addr));
}
__device__ __forceinline__ void mma16816(float* c, const unsigned int* a, const unsigned int* b) {
    asm volatile("mma.sync.aligned.m16n8k16.row.col.f32.bf16.bf16.f32 "
                 "{%0,%1,%2,%3}, {%4,%5,%6,%7}, {%8,%9}, {%0,%1,%2,%3};"
                 : "+f"(c[0]), "+f"(c[1]), "+f"(c[2]), "+f"(c[3])
                 : "r"(a[0]), "r"(a[1]), "r"(a[2]), "r"(a[3]), "r"(b[0]), "r"(b[1]));
}

__global__ __launch_bounds__(256) void logits_nll_k(
    const __nv_bfloat16* __restrict__ avh,
    const __nv_bfloat16* __restrict__ outWb,
    const float* __restrict__ out_b,
    const int* __restrict__ trg_tokens, int s,
    float* __restrict__ part_out, float* __restrict__ tgt_out)
{
    __shared__ __nv_bfloat16 As[128 * LSTRIDE];
    __shared__ __nv_bfloat16 Bs[128 * LSTRIDE];
    __shared__ int stgt[128];
    __shared__ float red[128][4];

    const int tid = threadIdx.x;
    const int lane = tid & 31;
    const int wid = tid >> 5;
    const int warp_m = wid >> 2;          // 0..1
    const int warp_n = wid & 3;           // 0..3
    const int m0 = warp_m * 64;
    const int n0w = warp_n * 32;
    const int nblk0 = blockIdx.x * 128;

    if (tid < 128) stgt[tid] = trg_tokens[tid * Tq + s + 1];

    float c[4][4][4];
#pragma unroll
    for (int mi = 0; mi < 4; mi++)
#pragma unroll
        for (int ni = 0; ni < 4; ni++)
#pragma unroll
            for (int q = 0; q < 4; q++) c[mi][ni][q] = 0.f;

    const unsigned int as_base = (unsigned int)__cvta_generic_to_shared(As);
    const unsigned int bs_base = (unsigned int)__cvta_generic_to_shared(Bs);

    const int ldrow = tid >> 3;
    const int ldc8 = (tid & 7) * 8;

    for (int kc = 0; kc < 8; kc++) {
        int k0 = kc * 64;
        __syncthreads();
#pragma unroll
        for (int p = 0; p < 4; p++) {
            int row = p * 32 + ldrow;
            *reinterpret_cast<uint4*>(&As[row * LSTRIDE + ldc8]) =
                *reinterpret_cast<const uint4*>(&avh[row * KP + k0 + ldc8]);
            *reinterpret_cast<uint4*>(&Bs[row * LSTRIDE + ldc8]) =
                *reinterpret_cast<const uint4*>(&outWb[(long)(nblk0 + row) * KP + k0 + ldc8]);
        }
        __syncthreads();

#pragma unroll
        for (int ks = 0; ks < 4; ks++) {
            int koff = ks * 16;
            unsigned int a[4][4], b[4][2];
#pragma unroll
            for (int mi = 0; mi < 4; mi++) {
                int r = m0 + mi * 16 + (lane & 15);
                int ccol = koff + (lane >> 4) * 8;
                ldsm4(a[mi], as_base + (unsigned int)(r * LSTRIDE + ccol) * 2u);
            }
#pragma unroll
            for (int ni = 0; ni < 4; ni++) {
                int r = n0w + ni * 8 + (lane & 7);
                int ccol = koff + ((lane >> 3) & 1) * 8;
                ldsm2(b[ni], bs_base + (unsigned int)(r * LSTRIDE + ccol) * 2u);
            }
#pragma unroll
            for (int mi = 0; mi < 4; mi++)
#pragma unroll
                for (int ni = 0; ni < 4; ni++) mma16816(c[mi][ni], a[mi], b[ni]);
        }
    }
    __syncthreads();

    // ---- epilogue: bias add, exp-sum per row, target logit capture ----
    const int gid = lane >> 2;
    const int tig = lane & 3;

#pragma unroll
    for (int mi = 0; mi < 4; mi++) {
        int r0 = m0 + mi * 16 + gid;
        int r1 = r0 + 8;
        int t0 = stgt[r0], t1 = stgt[r1];
        float s0 = 0.f, s1 = 0.f;
#pragma unroll
        for (int ni = 0; ni < 4; ni++) {
            int n = nblk0 + n0w + ni * 8 + tig * 2;
            float b0 = out_b[n], b1 = out_b[n + 1];
            float l00 = c[mi][ni][0] + b0, l01 = c[mi][ni][1] + b1;
            float l10 = c[mi][ni][2] + b0, l11 = c[mi][ni][3] + b1;
            s0 += expf(l00) + expf(l01);
            s1 += expf(l10) + expf(l11);
            if (n == t0) tgt_out[r0] = l00;
            if (n + 1 == t0) tgt_out[r0] = l01;
            if (n == t1) tgt_out[r1] = l10;
            if (n + 1 == t1) tgt_out[r1] = l11;
        }
        s0 += __shfl_xor_sync(0xffffffffu, s0, 1);
        s0 += __shfl_xor_sync(0xffffffffu, s0, 2);
        s1 += __shfl_xor_sync(0xffffffffu, s1, 1);
        s1 += __shfl_xor_sync(0xffffffffu, s1, 2);
        if (tig == 0) { red[r0][warp_n] = s0; red[r1][warp_n] = s1; }
    }
    __syncthreads();
    if (tid < 128)
        part_out[blockIdx.x * 128 + tid] = red[tid][0] + red[tid][1] + red[tid][2] + red[tid][3];
}

__global__ void nll_combine_k(const int* __restrict__ trg_lens, int s)
{
    int b = threadIdx.x;
    if (b < Bq) {
        float tot = 0.f;
        for (int i = 0; i < NBLK; i++) tot += g_part[i * Bq + b];
        float nll = logf(tot) - g_tgtlogit[b];
        g_nllbuf[s * Bq + b] = ((s + 1) < trg_lens[b]) ? -nll : 0.f;
    }
}

__global__ __launch_bounds__(256) void reduce_k(float* __restrict__ out)
{
    __shared__ float sm[256];
    float t = 0.f;
    for (int i = threadIdx.x; i < (Tq - 1) * Bq; i += 256) t += g_nllbuf[i];
    sm[threadIdx.x] = t;
    __syncthreads();
    for (int st = 128; st > 0; st >>= 1) {
        if (threadIdx.x < st) sm[threadIdx.x] += sm[threadIdx.x + st];
        __syncthreads();
    }
    if (threadIdx.x == 0) out[0] = sm[0];
}

// ---------------- launch ----------------
extern "C" void kernel_launch(void* const* d_in, const int* in_sizes, int n_in,
                              void* d_out, int out_size)
{
    const int*   src_tokens = (const int*)d_in[0];
    const int*   src_lens   = (const int*)d_in[1];
    const int*   trg_tokens = (const int*)d_in[2];
    const int*   trg_lens   = (const int*)d_in[3];
    const float* src_emb    = (const float*)d_in[4];
    const float* trg_emb    = (const float*)d_in[5];
    const float* enc_Wih0   = (const float*)d_in[6];
    const float* enc_Whh0   = (const float*)d_in[7];
    const float* enc_b0     = (const float*)d_in[8];
    const float* enc_Wih1   = (const float*)d_in[9];
    const float* enc_Whh1   = (const float*)d_in[10];
    const float* enc_b1     = (const float*)d_in[11];
    const float* dec_Wih    = (const float*)d_in[12];
    const float* dec_Whh    = (const float*)d_in[13];
    const float* dec_b      = (const float*)d_in[14];
    const float* hid_W      = (const float*)d_in[15];
    const float* hid_b      = (const float*)d_in[16];
    const float* out_W      = (const float*)d_in[17];
    const float* out_b      = (const float*)d_in[18];
    const float* init_W     = (const float*)d_in[19];
    const float* init_b     = (const float*)d_in[20];

    float *G0, *gates, *h1, *c1, *h2, *c2, *nh1, *S, *dh, *dc, *av, *ctx, *partp, *tgtp;
    __nv_bfloat16 *avh, *outWb;
    cudaGetSymbolAddress((void**)&G0, g_G0);
    cudaGetSymbolAddress((void**)&gates, g_gates);
    cudaGetSymbolAddress((void**)&h1, g_h1);
    cudaGetSymbolAddress((void**)&c1, g_c1);
    cudaGetSymbolAddress((void**)&h2, g_h2);
    cudaGetSymbolAddress((void**)&c2, g_c2);
    cudaGetSymbolAddress((void**)&nh1, g_nh1);
    cudaGetSymbolAddress((void**)&S, g_S);
    cudaGetSymbolAddress((void**)&dh, g_dh);
    cudaGetSymbolAddress((void**)&dc, g_dc);
    cudaGetSymbolAddress((void**)&av, g_av);
    cudaGetSymbolAddress((void**)&ctx, g_ctx);
    cudaGetSymbolAddress((void**)&avh, g_avh);
    cudaGetSymbolAddress((void**)&outWb, g_outWb);
    cudaGetSymbolAddress((void**)&partp, g_part);
    cudaGetSymbolAddress((void**)&tgtp, g_tgtlogit);

    const int cellBlocks = (Bq * Hq + 255) / 256;

    init_zero_k<<<cellBlocks, 256>>>(h1, c1, h2, c2, av);

    // out_W -> bf16 (once per launch)
    f2bf_k<<<(Vq * KP + 255) / 256, 256>>>(out_W, outWb, Vq * KP);

    // G0 = emb(src_tokens) @ Wih0^T + b0
    gemm_k<4, 4><<<dim3(Bq * Lq / 64, G4 / 64), 256>>>(
        G0, Bq * Lq, G4, nullptr, 0, enc_b0, 1,
        src_emb, src_tokens, 1, enc_Wih0, KP,
        nullptr, nullptr, 0, nullptr, 0,
        nullptr, nullptr, 0, nullptr, 0);

    // ---------------- encoder ----------------
    for (int t = 0; t < Lq; t++) {
        gemm_k<4, 2><<<dim3(Bq / 64, G4 / 32), 256>>>(
            gates, Bq, G4, G0 + (long)t * G4, Lq * G4, nullptr, 1,
            h1, nullptr, 0, enc_Whh0, KP,
            nullptr, nullptr, 0, nullptr, 0,
            nullptr, nullptr, 0, nullptr, 0);
        cell_k<<<cellBlocks, 256>>>(gates, h1, c1, nh1, nullptr, src_lens, t);

        gemm_k<4, 2><<<dim3(Bq / 64, G4 / 32), 256>>>(
            gates, Bq, G4, nullptr, 0, enc_b1, 2,
            nh1, nullptr, 0, enc_Wih1, KP,
            h2, nullptr, 0, enc_Whh1, KP,
            nullptr, nullptr, 0, nullptr, 0);
        cell_k<<<cellBlocks, 256>>>(gates, h2, c2, nullptr, S, src_lens, t);
    }

    // ---------------- decoder init ----------------
    gemm_k<2, 2><<<dim3(Bq / 32, Hq / 32), 256>>>(
        dc, Bq, Hq, nullptr, 0, init_b, 2,
        c1, nullptr, 0, init_W, 2 * Hq,
        c2, nullptr, 0, init_W + Hq, 2 * Hq,
        nullptr, nullptr, 0, nullptr, 0);
    tanh_k<<<cellBlocks, 256>>>(dh, dc);

    // ---------------- decoder ----------------
    for (int s = 0; s < Tq - 1; s++) {
        gemm_k<4, 2><<<dim3(Bq / 64, G4 / 32), 256>>>(
            gates, Bq, G4, nullptr, 0, dec_b, 3,
            trg_emb, trg_tokens + s, Tq, dec_Wih, Eq + Hq,
            av, nullptr, 0, dec_Wih + Eq, Eq + Hq,
            dh, nullptr, 0, dec_Whh, KP);
        cell_k<<<cellBlocks, 256>>>(gates, dh, dc, nullptr, nullptr, nullptr, 0);

        attn_k<<<Bq, 256>>>(dh, S, src_lens, ctx);

        gemm_k<2, 2><<<dim3(Bq / 32, Hq / 32), 256>>>(
            av, Bq, Hq, nullptr, 0, hid_b, 2,
            dh, nullptr, 0, hid_W, 2 * Hq,
            ctx, nullptr, 0, hid_W + Hq, 2 * Hq,
            nullptr, nullptr, 0, nullptr, 0);

        // av -> bf16 copy (recurrence keeps fp32 av)
        f2bf_k<<<cellBlocks, 256>>>(av, avh, Bq * Hq);

        // fused bf16 logits GEMM + exp-sum/target epilogue
        logits_nll_k<<<NBLK, 256>>>(avh, outWb, out_b, trg_tokens, s, partp, tgtp);
        nll_combine_k<<<1, 128>>>(trg_lens, s);
    }

    reduce_k<<<1, 256>>>((float*)d_out);
}

// round 5
// speedup vs baseline: 2.5499x; 1.6118x over previous
#include <cuda_runtime.h>
#include <cuda_bf16.h>
#include <math.h>
#include <stdint.h>

#define Bq 128
#define Lq 64
#define Tq 48
#define Eq 512
#define Hq 512
#define Vq 32000
#define G4 2048
#define KP 512
#define NBLK (Vq / 128)
#define LSTRIDE 72
#define HB (Bq * Hq)

// ---------------- fp32 scratch ----------------
__device__ float g_G0[Bq * Lq * G4];      // 64MB: x@Wih0^T + b0
__device__ float g_c1[HB], g_c2[HB];
__device__ float g_S[Bq * Lq * Hq];       // src_states fp32
__device__ float g_dh[HB], g_dc[HB];      // decoder h (fp32 for attn), c
__device__ float g_nllbuf[(Tq - 1) * Bq];
__device__ float g_part[NBLK * Bq];
__device__ float g_tgtlogit[Bq];

// ---------------- bf16 weights (converted once per launch) ----------------
__device__ __nv_bfloat16 g_Wih0b[G4 * KP], g_Whh0b[G4 * KP];
__device__ __nv_bfloat16 g_Wih1b[G4 * KP], g_Whh1b[G4 * KP];
__device__ __nv_bfloat16 g_dWihb[G4 * 1024], g_dWhhb[G4 * KP];
__device__ __nv_bfloat16 g_hidWb[Hq * 1024], g_initWb[Hq * 1024];
__device__ __nv_bfloat16 g_srcEmbB[Vq * Eq], g_trgEmbB[Vq * Eq];
__device__ __nv_bfloat16 g_outWb[Vq * KP];

// ---------------- bf16 states ----------------
__device__ __nv_bfloat16 g_h1b[2][HB], g_h2b[2][HB], g_dhb[2][HB];
__device__ __nv_bfloat16 g_nh1b[HB];
__device__ __nv_bfloat16 g_c1b[HB], g_c2b[HB];
__device__ __nv_bfloat16 g_ctxb[HB];
__device__ __nv_bfloat16 g_avh[HB];

// ---------------- MMA helpers (proven in R4) ----------------
__device__ __forceinline__ void ldsm4(unsigned int* r, unsigned int addr) {
    asm volatile("ldmatrix.sync.aligned.m8n8.x4.shared.b16 {%0,%1,%2,%3}, [%4];"
                 : "=r"(r[0]), "=r"(r[1]), "=r"(r[2]), "=r"(r[3]) : "r"(addr));
}
__device__ __forceinline__ void ldsm2(unsigned int* r, unsigned int addr) {
    asm volatile("ldmatrix.sync.aligned.m8n8.x2.shared.b16 {%0,%1}, [%2];"
                 : "=r"(r[0]), "=r"(r[1]) : "r"(addr));
}
__device__ __forceinline__ void mma16816(float* c, const unsigned int* a, const unsigned int* b) {
    asm volatile("mma.sync.aligned.m16n8k16.row.col.f32.bf16.bf16.f32 "
                 "{%0,%1,%2,%3}, {%4,%5,%6,%7}, {%8,%9}, {%0,%1,%2,%3};"
                 : "+f"(c[0]), "+f"(c[1]), "+f"(c[2]), "+f"(c[3])
                 : "r"(a[0]), "r"(a[1]), "r"(a[2]), "r"(a[3]), "r"(b[0]), "r"(b[1]));
}

// ============================================================
// Fused gates GEMM + LSTM cell. M=128, N=2048 (4 gates x 512).
// grid.x = 16; block bi owns columns j in [bi*32, bi*32+32) of EACH gate.
// B tile row r <-> W row (r>>5)*512 + nbase + (r&31); warp fragment ni = gate.
// Each thread ends up holding all 4 gate values of its (b,j) -> cell in regs.
// ============================================================
__global__ __launch_bounds__(256) void gates_cell_k(
    const __nv_bfloat16* __restrict__ A0, const int* __restrict__ map0, int ms0,
    const __nv_bfloat16* __restrict__ W0, int ldw0,
    const __nv_bfloat16* __restrict__ A1, const __nv_bfloat16* __restrict__ W1, int ldw1,
    const __nv_bfloat16* __restrict__ A2, const __nv_bfloat16* __restrict__ W2, int ldw2,
    int npairs,
    const float* __restrict__ initp, long initStride,
    const float* __restrict__ bias,
    const int* __restrict__ lens, int t,
    const __nv_bfloat16* __restrict__ hbf_in, __nv_bfloat16* __restrict__ hbf_out,
    float* __restrict__ c_f,
    __nv_bfloat16* __restrict__ nh_bf_out, float* __restrict__ S_out,
    float* __restrict__ h_f_out)
{
    __shared__ __nv_bfloat16 As[128 * LSTRIDE];
    __shared__ __nv_bfloat16 Bs[128 * LSTRIDE];

    const int tid = threadIdx.x;
    const int lane = tid & 31;
    const int wid = tid >> 5;
    const int warp_m = wid >> 2;
    const int warp_n = wid & 3;
    const int m0 = warp_m * 64;
    const int nbase = blockIdx.x * 32;

    float c[4][4][4];
#pragma unroll
    for (int mi = 0; mi < 4; mi++)
#pragma unroll
        for (int ni = 0; ni < 4; ni++)
#pragma unroll
            for (int q = 0; q < 4; q++) c[mi][ni][q] = 0.f;

    const unsigned int as_base = (unsigned int)__cvta_generic_to_shared(As);
    const unsigned int bs_base = (unsigned int)__cvta_generic_to_shared(Bs);
    const int ldrow = tid >> 3;
    const int ldc8 = (tid & 7) * 8;

    const __nv_bfloat16* Aps[3] = {A0, A1, A2};
    const __nv_bfloat16* Wps[3] = {W0, W1, W2};
    const int lws[3] = {ldw0, ldw1, ldw2};

    for (int p = 0; p < npairs; p++) {
        const __nv_bfloat16* A = Aps[p];
        const __nv_bfloat16* W = Wps[p];
        const int ldw = lws[p];
        for (int kc = 0; kc < 8; kc++) {
            int k0 = kc * 64;
            __syncthreads();
#pragma unroll
            for (int q4 = 0; q4 < 4; q4++) {
                int row = q4 * 32 + ldrow;
                long arow;
                if (p == 0 && map0) arow = (long)map0[row * ms0] * 512;
                else arow = (long)row * 512;
                *reinterpret_cast<uint4*>(&As[row * LSTRIDE + ldc8]) =
                    *reinterpret_cast<const uint4*>(&A[arow + k0 + ldc8]);
                int wrow = ((row >> 5) * 512) + nbase + (row & 31);
                *reinterpret_cast<uint4*>(&Bs[row * LSTRIDE + ldc8]) =
                    *reinterpret_cast<const uint4*>(&W[(long)wrow * ldw + k0 + ldc8]);
            }
            __syncthreads();

#pragma unroll
            for (int ks = 0; ks < 4; ks++) {
                int koff = ks * 16;
                unsigned int a[4][4], b[4][2];
#pragma unroll
                for (int mi = 0; mi < 4; mi++) {
                    int r = m0 + mi * 16 + (lane & 15);
                    int ccol = koff + (lane >> 4) * 8;
                    ldsm4(a[mi], as_base + (unsigned int)(r * LSTRIDE + ccol) * 2u);
                }
#pragma unroll
                for (int ni = 0; ni < 4; ni++) {
                    int r = ni * 32 + warp_n * 8 + (lane & 7);   // gate = ni
                    int ccol = koff + ((lane >> 3) & 1) * 8;
                    ldsm2(b[ni], bs_base + (unsigned int)(r * LSTRIDE + ccol) * 2u);
                }
#pragma unroll
                for (int mi = 0; mi < 4; mi++)
#pragma unroll
                    for (int ni = 0; ni < 4; ni++) mma16816(c[mi][ni], a[mi], b[ni]);
            }
        }
    }

    // ---- cell epilogue (all 4 gates in-thread) ----
#pragma unroll
    for (int mi = 0; mi < 4; mi++) {
#pragma unroll
        for (int t2 = 0; t2 < 2; t2++) {
            int row = m0 + mi * 16 + (lane >> 2) + 8 * t2;
#pragma unroll
            for (int u = 0; u < 2; u++) {
                int j = nbase + warp_n * 8 + 2 * (lane & 3) + u;
                int e = 2 * t2 + u;
                float gi = c[mi][0][e], gf = c[mi][1][e], gg = c[mi][2][e], go = c[mi][3][e];
                if (initp) {
                    const float* ip = initp + (long)row * initStride;
                    gi += ip[j]; gf += ip[512 + j]; gg += ip[1024 + j]; go += ip[1536 + j];
                }
                if (bias) {
                    gi += bias[j]; gf += bias[512 + j]; gg += bias[1024 + j]; go += bias[1536 + j];
                }
                float i_ = 1.f / (1.f + expf(-gi));
                float f_ = 1.f / (1.f + expf(-gf));
                float tg = tanhf(gg);
                float o_ = 1.f / (1.f + expf(-go));
                int idx = row * 512 + j;
                float cn = f_ * c_f[idx] + i_ * tg;
                float hn = o_ * tanhf(cn);
                bool mk = lens ? (t < lens[row]) : true;
                if (nh_bf_out) nh_bf_out[idx] = __float2bfloat16_rn(hn);
                if (S_out) S_out[(long)row * Lq * 512 + (long)t * 512 + j] = mk ? hn : 0.f;
                if (h_f_out) h_f_out[idx] = hn;
                if (mk) { c_f[idx] = cn; hbf_out[idx] = __float2bfloat16_rn(hn); }
                else hbf_out[idx] = hbf_in[idx];
            }
        }
    }
}

// ============================================================
// Generic bf16 HMMA GEMM (linear epilogue). M = grid.x*128, N = grid.y*128.
// outBF stores tanh(val) if outTanhF given, else val.
// ============================================================
__global__ __launch_bounds__(256) void hgemm_k(
    const __nv_bfloat16* __restrict__ A0, const int* __restrict__ map0, int ms0,
    const __nv_bfloat16* __restrict__ W0, int ldw0,
    const __nv_bfloat16* __restrict__ A1, const __nv_bfloat16* __restrict__ W1, int ldw1,
    int npairs,
    const float* __restrict__ bias, int N,
    float* __restrict__ outRaw, float* __restrict__ outTanhF,
    __nv_bfloat16* __restrict__ outBF)
{
    __shared__ __nv_bfloat16 As[128 * LSTRIDE];
    __shared__ __nv_bfloat16 Bs[128 * LSTRIDE];

    const int tid = threadIdx.x;
    const int lane = tid & 31;
    const int wid = tid >> 5;
    const int warp_m = wid >> 2;
    const int warp_n = wid & 3;
    const int m0 = warp_m * 64;
    const int mblk0 = blockIdx.x * 128;
    const int nblk0 = blockIdx.y * 128;

    float c[4][4][4];
#pragma unroll
    for (int mi = 0; mi < 4; mi++)
#pragma unroll
        for (int ni = 0; ni < 4; ni++)
#pragma unroll
            for (int q = 0; q < 4; q++) c[mi][ni][q] = 0.f;

    const unsigned int as_base = (unsigned int)__cvta_generic_to_shared(As);
    const unsigned int bs_base = (unsigned int)__cvta_generic_to_shared(Bs);
    const int ldrow = tid >> 3;
    const int ldc8 = (tid & 7) * 8;

    const __nv_bfloat16* Aps[2] = {A0, A1};
    const __nv_bfloat16* Wps[2] = {W0, W1};
    const int lws[2] = {ldw0, ldw1};

    for (int p = 0; p < npairs; p++) {
        const __nv_bfloat16* A = Aps[p];
        const __nv_bfloat16* W = Wps[p];
        const int ldw = lws[p];
        for (int kc = 0; kc < 8; kc++) {
            int k0 = kc * 64;
            __syncthreads();
#pragma unroll
            for (int q4 = 0; q4 < 4; q4++) {
                int row = q4 * 32 + ldrow;
                int gm = mblk0 + row;
                long arow;
                if (p == 0 && map0) arow = (long)map0[gm * ms0] * 512;
                else arow = (long)gm * 512;
                *reinterpret_cast<uint4*>(&As[row * LSTRIDE + ldc8]) =
                    *reinterpret_cast<const uint4*>(&A[arow + k0 + ldc8]);
                *reinterpret_cast<uint4*>(&Bs[row * LSTRIDE + ldc8]) =
                    *reinterpret_cast<const uint4*>(&W[(long)(nblk0 + row) * ldw + k0 + ldc8]);
            }
            __syncthreads();

#pragma unroll
            for (int ks = 0; ks < 4; ks++) {
                int koff = ks * 16;
                unsigned int a[4][4], b[4][2];
#pragma unroll
                for (int mi = 0; mi < 4; mi++) {
                    int r = m0 + mi * 16 + (lane & 15);
                    int ccol = koff + (lane >> 4) * 8;
                    ldsm4(a[mi], as_base + (unsigned int)(r * LSTRIDE + ccol) * 2u);
                }
#pragma unroll
                for (int ni = 0; ni < 4; ni++) {
                    int r = warp_n * 32 + ni * 8 + (lane & 7);
                    int ccol = koff + ((lane >> 3) & 1) * 8;
                    ldsm2(b[ni], bs_base + (unsigned int)(r * LSTRIDE + ccol) * 2u);
                }
#pragma unroll
                for (int mi = 0; mi < 4; mi++)
#pragma unroll
                    for (int ni = 0; ni < 4; ni++) mma16816(c[mi][ni], a[mi], b[ni]);
            }
        }
    }

#pragma unroll
    for (int mi = 0; mi < 4; mi++) {
#pragma unroll
        for (int ni = 0; ni < 4; ni++) {
#pragma unroll
            for (int t2 = 0; t2 < 2; t2++) {
                int gm = mblk0 + m0 + mi * 16 + (lane >> 2) + 8 * t2;
#pragma unroll
                for (int u = 0; u < 2; u++) {
                    int n = nblk0 + warp_n * 32 + ni * 8 + 2 * (lane & 3) + u;
                    float v = c[mi][ni][2 * t2 + u];
                    if (bias) v += bias[n];
                    long oi = (long)gm * N + n;
                    if (outRaw) outRaw[oi] = v;
                    float tv = v;
                    if (outTanhF) { tv = tanhf(v); outTanhF[oi] = tv; }
                    if (outBF) outBF[oi] = __float2bfloat16_rn(outTanhF ? tv : v);
                }
            }
        }
    }
}

// ---------------- misc small kernels ----------------
__global__ void init_zero_k()
{
    int i = blockIdx.x * 256 + threadIdx.x;
    if (i < HB) {
        g_h1b[0][i] = __float2bfloat16(0.f);
        g_h2b[0][i] = __float2bfloat16(0.f);
        g_avh[i] = __float2bfloat16(0.f);
        g_c1[i] = 0.f; g_c2[i] = 0.f;
    }
}

__global__ void f2bf_k(const float* __restrict__ in, __nv_bfloat16* __restrict__ out, int n)
{
    int i = blockIdx.x * 256 + threadIdx.x;
    if (i < n) out[i] = __float2bfloat16_rn(in[i]);
}

// ---------------- attention (fp32 in, bf16 ctx out) ----------------
__global__ __launch_bounds__(256) void attn_k(
    const float* __restrict__ dh, const float* __restrict__ S,
    const int* __restrict__ slens, __nv_bfloat16* __restrict__ ctxb)
{
    int b = blockIdx.x;
    __shared__ float sh[Hq];
    __shared__ float part[Lq][4];
    __shared__ float sc[Lq];
    __shared__ float sinv;
    int tid = threadIdx.x;
    sh[tid] = dh[(long)b * Hq + tid];
    sh[tid + 256] = dh[(long)b * Hq + tid + 256];
    __syncthreads();

    int l = tid >> 2, q = tid & 3;
    const float* Sb = S + (long)b * Lq * Hq + (long)l * Hq + q * 128;
    float p = 0.f;
#pragma unroll 8
    for (int k = 0; k < 128; k++) p = fmaf(sh[q * 128 + k], Sb[k], p);
    part[l][q] = p;
    __syncthreads();

    if (tid < Lq) {
        float s = part[tid][0] + part[tid][1] + part[tid][2] + part[tid][3];
        if (tid >= slens[b]) s = -1e9f;
        sc[tid] = expf(s);
    }
    __syncthreads();
    if (tid == 0) {
        float tsum = 0.f;
        for (int i = 0; i < Lq; i++) tsum += sc[i];
        sinv = 1.f / tsum;
    }
    __syncthreads();
    if (tid < Lq) sc[tid] *= sinv;
    __syncthreads();

    for (int j = tid; j < Hq; j += 256) {
        const float* Sb2 = S + (long)b * Lq * Hq + j;
        float acc = 0.f;
#pragma unroll 8
        for (int l2 = 0; l2 < Lq; l2++) acc = fmaf(sc[l2], Sb2[(long)l2 * Hq], acc);
        ctxb[(long)b * Hq + j] = __float2bfloat16_rn(acc);
    }
}

// ---------------- logits GEMM + fused NLL pieces (proven in R4) ----------------
__global__ __launch_bounds__(256) void logits_nll_k(
    const __nv_bfloat16* __restrict__ avh,
    const __nv_bfloat16* __restrict__ outWb,
    const float* __restrict__ out_b,
    const int* __restrict__ trg_tokens, int s,
    float* __restrict__ part_out, float* __restrict__ tgt_out)
{
    __shared__ __nv_bfloat16 As[128 * LSTRIDE];
    __shared__ __nv_bfloat16 Bs[128 * LSTRIDE];
    __shared__ int stgt[128];
    __shared__ float red[128][4];

    const int tid = threadIdx.x;
    const int lane = tid & 31;
    const int wid = tid >> 5;
    const int warp_m = wid >> 2;
    const int warp_n = wid & 3;
    const int m0 = warp_m * 64;
    const int n0w = warp_n * 32;
    const int nblk0 = blockIdx.x * 128;

    if (tid < 128) stgt[tid] = trg_tokens[tid * Tq + s + 1];

    float c[4][4][4];
#pragma unroll
    for (int mi = 0; mi < 4; mi++)
#pragma unroll
        for (int ni = 0; ni < 4; ni++)
#pragma unroll
            for (int q = 0; q < 4; q++) c[mi][ni][q] = 0.f;

    const unsigned int as_base = (unsigned int)__cvta_generic_to_shared(As);
    const unsigned int bs_base = (unsigned int)__cvta_generic_to_shared(Bs);
    const int ldrow = tid >> 3;
    const int ldc8 = (tid & 7) * 8;

    for (int kc = 0; kc < 8; kc++) {
        int k0 = kc * 64;
        __syncthreads();
#pragma unroll
        for (int p = 0; p < 4; p++) {
            int row = p * 32 + ldrow;
            *reinterpret_cast<uint4*>(&As[row * LSTRIDE + ldc8]) =
                *reinterpret_cast<const uint4*>(&avh[row * KP + k0 + ldc8]);
            *reinterpret_cast<uint4*>(&Bs[row * LSTRIDE + ldc8]) =
                *reinterpret_cast<const uint4*>(&outWb[(long)(nblk0 + row) * KP + k0 + ldc8]);
        }
        __syncthreads();

#pragma unroll
        for (int ks = 0; ks < 4; ks++) {
            int koff = ks * 16;
            unsigned int a[4][4], b[4][2];
#pragma unroll
            for (int mi = 0; mi < 4; mi++) {
                int r = m0 + mi * 16 + (lane & 15);
                int ccol = koff + (lane >> 4) * 8;
                ldsm4(a[mi], as_base + (unsigned int)(r * LSTRIDE + ccol) * 2u);
            }
#pragma unroll
            for (int ni = 0; ni < 4; ni++) {
                int r = n0w + ni * 8 + (lane & 7);
                int ccol = koff + ((lane >> 3) & 1) * 8;
                ldsm2(b[ni], bs_base + (unsigned int)(r * LSTRIDE + ccol) * 2u);
            }
#pragma unroll
            for (int mi = 0; mi < 4; mi++)
#pragma unroll
                for (int ni = 0; ni < 4; ni++) mma16816(c[mi][ni], a[mi], b[ni]);
        }
    }
    __syncthreads();

    const int gid = lane >> 2;
    const int tig = lane & 3;

#pragma unroll
    for (int mi = 0; mi < 4; mi++) {
        int r0 = m0 + mi * 16 + gid;
        int r1 = r0 + 8;
        int t0 = stgt[r0], t1 = stgt[r1];
        float s0 = 0.f, s1 = 0.f;
#pragma unroll
        for (int ni = 0; ni < 4; ni++) {
            int n = nblk0 + n0w + ni * 8 + tig * 2;
            float b0 = out_b[n], b1 = out_b[n + 1];
            float l00 = c[mi][ni][0] + b0, l01 = c[mi][ni][1] + b1;
            float l10 = c[mi][ni][2] + b0, l11 = c[mi][ni][3] + b1;
            s0 += expf(l00) + expf(l01);
            s1 += expf(l10) + expf(l11);
            if (n == t0) tgt_out[r0] = l00;
            if (n + 1 == t0) tgt_out[r0] = l01;
            if (n == t1) tgt_out[r1] = l10;
            if (n + 1 == t1) tgt_out[r1] = l11;
        }
        s0 += __shfl_xor_sync(0xffffffffu, s0, 1);
        s0 += __shfl_xor_sync(0xffffffffu, s0, 2);
        s1 += __shfl_xor_sync(0xffffffffu, s1, 1);
        s1 += __shfl_xor_sync(0xffffffffu, s1, 2);
        if (tig == 0) { red[r0][warp_n] = s0; red[r1][warp_n] = s1; }
    }
    __syncthreads();
    if (tid < 128)
        part_out[blockIdx.x * 128 + tid] = red[tid][0] + red[tid][1] + red[tid][2] + red[tid][3];
}

__global__ void nll_combine_k(const int* __restrict__ trg_lens, int s)
{
    int b = threadIdx.x;
    if (b < Bq) {
        float tot = 0.f;
        for (int i = 0; i < NBLK; i++) tot += g_part[i * Bq + b];
        float nll = logf(tot) - g_tgtlogit[b];
        g_nllbuf[s * Bq + b] = ((s + 1) < trg_lens[b]) ? -nll : 0.f;
    }
}

__global__ __launch_bounds__(256) void reduce_k(float* __restrict__ out)
{
    __shared__ float sm[256];
    float t = 0.f;
    for (int i = threadIdx.x; i < (Tq - 1) * Bq; i += 256) t += g_nllbuf[i];
    sm[threadIdx.x] = t;
    __syncthreads();
    for (int st = 128; st > 0; st >>= 1) {
        if (threadIdx.x < st) sm[threadIdx.x] += sm[threadIdx.x + st];
        __syncthreads();
    }
    if (threadIdx.x == 0) out[0] = sm[0];
}

// ---------------- launch ----------------
extern "C" void kernel_launch(void* const* d_in, const int* in_sizes, int n_in,
                              void* d_out, int out_size)
{
    const int*   src_tokens = (const int*)d_in[0];
    const int*   src_lens   = (const int*)d_in[1];
    const int*   trg_tokens = (const int*)d_in[2];
    const int*   trg_lens   = (const int*)d_in[3];
    const float* src_emb    = (const float*)d_in[4];
    const float* trg_emb    = (const float*)d_in[5];
    const float* enc_Wih0   = (const float*)d_in[6];
    const float* enc_Whh0   = (const float*)d_in[7];
    const float* enc_b0     = (const float*)d_in[8];
    const float* enc_Wih1   = (const float*)d_in[9];
    const float* enc_Whh1   = (const float*)d_in[10];
    const float* enc_b1     = (const float*)d_in[11];
    const float* dec_Wih    = (const float*)d_in[12];
    const float* dec_Whh    = (const float*)d_in[13];
    const float* dec_b      = (const float*)d_in[14];
    const float* hid_W      = (const float*)d_in[15];
    const float* hid_b      = (const float*)d_in[16];
    const float* out_W      = (const float*)d_in[17];
    const float* out_b      = (const float*)d_in[18];
    const float* init_W     = (const float*)d_in[19];
    const float* init_b     = (const float*)d_in[20];

    float *G0, *c1, *c2, *S, *dh, *dc, *partp, *tgtp;
    __nv_bfloat16 *Wih0b, *Whh0b, *Wih1b, *Whh1b, *dWihb, *dWhhb, *hidWb, *initWb;
    __nv_bfloat16 *srcEmbB, *trgEmbB, *outWb, *avh, *nh1b, *c1b, *c2b, *ctxb;
    __nv_bfloat16 *h1b0, *h1b1, *h2b0, *h2b1, *dhb0, *dhb1;

    cudaGetSymbolAddress((void**)&G0, g_G0);
    cudaGetSymbolAddress((void**)&c1, g_c1);
    cudaGetSymbolAddress((void**)&c2, g_c2);
    cudaGetSymbolAddress((void**)&S, g_S);
    cudaGetSymbolAddress((void**)&dh, g_dh);
    cudaGetSymbolAddress((void**)&dc, g_dc);
    cudaGetSymbolAddress((void**)&partp, g_part);
    cudaGetSymbolAddress((void**)&tgtp, g_tgtlogit);
    cudaGetSymbolAddress((void**)&Wih0b, g_Wih0b);
    cudaGetSymbolAddress((void**)&Whh0b, g_Whh0b);
    cudaGetSymbolAddress((void**)&Wih1b, g_Wih1b);
    cudaGetSymbolAddress((void**)&Whh1b, g_Whh1b);
    cudaGetSymbolAddress((void**)&dWihb, g_dWihb);
    cudaGetSymbolAddress((void**)&dWhhb, g_dWhhb);
    cudaGetSymbolAddress((void**)&hidWb, g_hidWb);
    cudaGetSymbolAddress((void**)&initWb, g_initWb);
    cudaGetSymbolAddress((void**)&srcEmbB, g_srcEmbB);
    cudaGetSymbolAddress((void**)&trgEmbB, g_trgEmbB);
    cudaGetSymbolAddress((void**)&outWb, g_outWb);
    cudaGetSymbolAddress((void**)&avh, g_avh);
    cudaGetSymbolAddress((void**)&nh1b, g_nh1b);
    cudaGetSymbolAddress((void**)&c1b, g_c1b);
    cudaGetSymbolAddress((void**)&c2b, g_c2b);
    cudaGetSymbolAddress((void**)&ctxb, g_ctxb);
    cudaGetSymbolAddress((void**)&h1b0, g_h1b); h1b1 = h1b0 + HB;
    cudaGetSymbolAddress((void**)&h2b0, g_h2b); h2b1 = h2b0 + HB;
    cudaGetSymbolAddress((void**)&dhb0, g_dhb); dhb1 = dhb0 + HB;
    __nv_bfloat16* h1b[2] = {h1b0, h1b1};
    __nv_bfloat16* h2b[2] = {h2b0, h2b1};
    __nv_bfloat16* dhb[2] = {dhb0, dhb1};

    const int cb = (HB + 255) / 256;

    init_zero_k<<<cb, 256>>>();

    // weight / embedding conversions (once per launch)
    f2bf_k<<<(G4 * KP + 255) / 256, 256>>>(enc_Wih0, Wih0b, G4 * KP);
    f2bf_k<<<(G4 * KP + 255) / 256, 256>>>(enc_Whh0, Whh0b, G4 * KP);
    f2bf_k<<<(G4 * KP + 255) / 256, 256>>>(enc_Wih1, Wih1b, G4 * KP);
    f2bf_k<<<(G4 * KP + 255) / 256, 256>>>(enc_Whh1, Whh1b, G4 * KP);
    f2bf_k<<<(G4 * 1024 + 255) / 256, 256>>>(dec_Wih, dWihb, G4 * 1024);
    f2bf_k<<<(G4 * KP + 255) / 256, 256>>>(dec_Whh, dWhhb, G4 * KP);
    f2bf_k<<<(Hq * 1024 + 255) / 256, 256>>>(hid_W, hidWb, Hq * 1024);
    f2bf_k<<<(Hq * 1024 + 255) / 256, 256>>>(init_W, initWb, Hq * 1024);
    f2bf_k<<<(Vq * Eq + 255) / 256, 256>>>(src_emb, srcEmbB, Vq * Eq);
    f2bf_k<<<(Vq * Eq + 255) / 256, 256>>>(trg_emb, trgEmbB, Vq * Eq);
    f2bf_k<<<(Vq * KP + 255) / 256, 256>>>(out_W, outWb, Vq * KP);

    // G0 = emb(src) @ Wih0^T + b0   (M=8192, N=2048)
    hgemm_k<<<dim3(Bq * Lq / 128, G4 / 128), 256>>>(
        srcEmbB, src_tokens, 1, Wih0b, KP,
        nullptr, nullptr, 0, 1,
        enc_b0, G4, G0, nullptr, nullptr);

    // ---------------- encoder ----------------
    for (int t = 0; t < Lq; t++) {
        int p = t & 1;
        // layer0: gates = G0[:,t,:] + h1 @ Whh0^T  -> cell -> h1,c1, nh1
        gates_cell_k<<<16, 256>>>(
            h1b[p], nullptr, 0, Whh0b, KP,
            nullptr, nullptr, 0, nullptr, nullptr, 0, 1,
            G0 + (long)t * G4, (long)Lq * G4,
            nullptr, src_lens, t,
            h1b[p], h1b[1 - p], c1,
            nh1b, nullptr, nullptr);
        // layer1: gates = nh1 @ Wih1^T + h2 @ Whh1^T + b1 -> cell -> h2,c2, S[t]
        gates_cell_k<<<16, 256>>>(
            nh1b, nullptr, 0, Wih1b, KP,
            h2b[p], Whh1b, KP, nullptr, nullptr, 0, 2,
            nullptr, 0,
            enc_b1, src_lens, t,
            h2b[p], h2b[1 - p], c2,
            nullptr, S, nullptr);
    }

    // decoder init: c0 = [c1,c2] @ init_W^T + init_b ; h0 = tanh(c0)
    f2bf_k<<<cb, 256>>>(c1, c1b, HB);
    f2bf_k<<<cb, 256>>>(c2, c2b, HB);
    hgemm_k<<<dim3(1, Hq / 128), 256>>>(
        c1b, nullptr, 0, initWb, 1024,
        c2b, initWb + 512, 1024, 2,
        init_b, Hq, dc, dh, dhb[0]);

    // ---------------- decoder ----------------
    for (int s = 0; s < Tq - 1; s++) {
        int p = s & 1;
        // gates = [v, av] @ dec_Wih^T + h @ dec_Whh^T + b -> cell -> dh, dc
        gates_cell_k<<<16, 256>>>(
            trgEmbB, trg_tokens + s, Tq, dWihb, 1024,
            avh, dWihb + 512, 1024,
            dhb[p], dWhhb, KP, 3,
            nullptr, 0,
            dec_b, nullptr, 0,
            dhb[p], dhb[1 - p], dc,
            nullptr, nullptr, dh);

        attn_k<<<Bq, 256>>>(dh, S, src_lens, ctxb);

        // av = [h, ctx] @ hid_W^T + hid_b  -> bf16 avh
        hgemm_k<<<dim3(1, Hq / 128), 256>>>(
            dhb[1 - p], nullptr, 0, hidWb, 1024,
            ctxb, hidWb + 512, 1024, 2,
            hid_b, Hq, nullptr, nullptr, avh);

        logits_nll_k<<<NBLK, 256>>>(avh, outWb, out_b, trg_tokens, s, partp, tgtp);
        nll_combine_k<<<1, 128>>>(trg_lens, s);
    }

    reduce_k<<<1, 256>>>((float*)d_out);
}